// round 4
// baseline (speedup 1.0000x reference)
#include <cuda_runtime.h>

// state: (2,)^24 + (4,) float32, row-major. qubit q axis stride = 2^(23-q)*4 elems.
// TARGETS = (5, 12): stride_q5 = 2^18 float4; stride_q12 = 2^11 float4.
// out[a,b] = sum_{i,j} P[(a*2+b)*4 + (i*2+j)] * s[i@q5, j@q12]   (batch in float4 lanes)
//
// Persistent grid-stride: grid sized to exactly one wave (148 SMs x 8 CTAs),
// each thread loops over rest-indices. Stores are fire-and-forget, so the
// next iteration's 4 LDG.128s issue immediately after the STGs -> the LSU
// pipeline never drains at tile boundaries (unlike 16384 one-shot CTAs).

#define S12_V (1u << 11)
#define S5_V  (1u << 18)
#define NREST (1u << 22)

__global__ void __launch_bounds__(256, 8) gate2q_kernel(
    const float4* __restrict__ state,
    const float*  __restrict__ pauli,
    float4*       __restrict__ out)
{
    float p[16];
#pragma unroll
    for (int i = 0; i < 16; ++i) p[i] = __ldg(pauli + i);

    const unsigned stride = gridDim.x * blockDim.x;

    for (unsigned t = blockIdx.x * blockDim.x + threadIdx.x; t < NREST; t += stride) {
        // Insert zero bits at positions 11 and 18 of the float4 index.
        unsigned idx = (t & 0x7FFu)
                     | (((t >> 11) & 0x3Fu) << 12)
                     | ((t >> 17) << 19);

        float4 s00 = __ldcs(state + idx);
        float4 s01 = __ldcs(state + idx + S12_V);
        float4 s10 = __ldcs(state + idx + S5_V);
        float4 s11 = __ldcs(state + idx + S5_V + S12_V);

#pragma unroll
        for (int r = 0; r < 4; ++r) {
            float a = p[r * 4 + 0], b = p[r * 4 + 1], c = p[r * 4 + 2], d = p[r * 4 + 3];
            float4 o;
            o.x = fmaf(a, s00.x, fmaf(b, s01.x, fmaf(c, s10.x, d * s11.x)));
            o.y = fmaf(a, s00.y, fmaf(b, s01.y, fmaf(c, s10.y, d * s11.y)));
            o.z = fmaf(a, s00.z, fmaf(b, s01.z, fmaf(c, s10.z, d * s11.z)));
            o.w = fmaf(a, s00.w, fmaf(b, s01.w, fmaf(c, s10.w, d * s11.w)));
            unsigned dst = idx + (r >> 1) * S5_V + (r & 1) * S12_V;
            __stcs(out + dst, o);
        }
    }
}

extern "C" void kernel_launch(void* const* d_in, const int* in_sizes, int n_in,
                              void* d_out, int out_size)
{
    const float4* state = (const float4*)d_in[0];
    const float*  pauli = (const float*)d_in[1];
    float4*       out   = (float4*)d_out;

    const int n_ctas = 148 * 8;   // one full wave at occ=8
    gate2q_kernel<<<n_ctas, 256>>>(state, pauli, out);
}

// round 5
// speedup vs baseline: 1.2006x; 1.2006x over previous
#include <cuda_runtime.h>

// state: (2,)^24 + (4,) float32, row-major. qubit q axis stride = 2^(23-q)*4 elems.
// TARGETS = (5, 12): stride_q5 = 2^18 float4; stride_q12 = 2^11 float4.
// out[a,b] = sum_{i,j} P[(a*2+b)*4 + (i*2+j)] * s[i@q5, j@q12]   (batch in float4 lanes)
//
// One-shot, 1 rest-index per thread (proven best: CTA churn = prefetch).
// block=128 for finer CTA-replacement granularity: 16 CTA slots/SM, 4-warp
// quanta, fresh load-issuing warps arrive 2x as often as with block=256.

#define S12_V (1u << 11)   // qubit-12 stride in float4 units
#define S5_V  (1u << 18)   // qubit-5  stride in float4 units

__global__ void __launch_bounds__(128) gate2q_kernel(
    const float4* __restrict__ state,
    const float*  __restrict__ pauli,
    float4*       __restrict__ out)
{
    unsigned t = blockIdx.x * blockDim.x + threadIdx.x;   // t in [0, 2^22)

    // Insert zero bits at positions 11 and 18 of the float4 index.
    unsigned idx = (t & 0x7FFu)                    // bits 0..10
                 | (((t >> 11) & 0x3Fu) << 12)     // 6 bits -> 12..17
                 | ((t >> 17) << 19);              // 5 bits -> 19..23

    // Load the 4 coupled amplitudes (streaming — no reuse anywhere).
    float4 s00 = __ldcs(state + idx);                 // q5=0, q12=0
    float4 s01 = __ldcs(state + idx + S12_V);         // q5=0, q12=1
    float4 s10 = __ldcs(state + idx + S5_V);          // q5=1, q12=0
    float4 s11 = __ldcs(state + idx + S5_V + S12_V);  // q5=1, q12=1

    float p[16];
#pragma unroll
    for (int i = 0; i < 16; ++i) p[i] = __ldg(pauli + i);

#pragma unroll
    for (int r = 0; r < 4; ++r) {
        float a = p[r * 4 + 0], b = p[r * 4 + 1], c = p[r * 4 + 2], d = p[r * 4 + 3];
        float4 o;
        o.x = fmaf(a, s00.x, fmaf(b, s01.x, fmaf(c, s10.x, d * s11.x)));
        o.y = fmaf(a, s00.y, fmaf(b, s01.y, fmaf(c, s10.y, d * s11.y)));
        o.z = fmaf(a, s00.z, fmaf(b, s01.z, fmaf(c, s10.z, d * s11.z)));
        o.w = fmaf(a, s00.w, fmaf(b, s01.w, fmaf(c, s10.w, d * s11.w)));
        unsigned dst = idx + (r >> 1) * S5_V + (r & 1) * S12_V;
        __stcs(out + dst, o);
    }
}

extern "C" void kernel_launch(void* const* d_in, const int* in_sizes, int n_in,
                              void* d_out, int out_size)
{
    const float4* state = (const float4*)d_in[0];   // 2^26 floats = 2^24 float4
    const float*  pauli = (const float*)d_in[1];    // 16 floats
    float4*       out   = (float4*)d_out;

    const unsigned n_threads = 1u << 22;            // one per rest-index
    gate2q_kernel<<<n_threads / 128, 128>>>(state, pauli, out);
}

// round 6
// speedup vs baseline: 1.2011x; 1.0004x over previous
#include <cuda_runtime.h>

// state: (2,)^24 + (4,) float32, row-major. qubit q axis stride = 2^(23-q)*4 elems.
// TARGETS = (5, 12): stride_q5 = 2^20 elems = 2^18 float4; stride_q12 = 2^13 elems = 2^11 float4.
// out[a,b] (bits at q5=a, q12=b) = sum_{i,j} P[a*2+b, i*2+j] * s[i at q5, j at q12].
//
// LOCKED OPTIMUM (R1 structure): one-shot CTAs, 1 rest-index/thread, 32 regs,
// occ ~80%, 4 front-batched LDG.128 per thread. Measured 74.5us kernel at
// 6.46 TB/s = 81% DRAM-active; residual idle is HBM R/W turnaround + refresh
// (compulsory traffic only, latency fully hidden) -> physical floor.
// Falsified alternatives: 2x unroll (59 regs, occ 40%, 87us), persistent
// grid-stride (LSU drains per iteration, 94us), block=128 & cache hints (neutral).

#define S12_V (1u << 11)   // qubit-12 stride in float4 units
#define S5_V  (1u << 18)   // qubit-5  stride in float4 units

__global__ void __launch_bounds__(256) gate2q_kernel(
    const float4* __restrict__ state,
    const float*  __restrict__ pauli,
    float4*       __restrict__ out)
{
    unsigned t = blockIdx.x * blockDim.x + threadIdx.x;   // t in [0, 2^22)

    // Insert zero bits at positions 11 and 18 of the float4 index.
    unsigned idx = (t & 0x7FFu)                    // bits 0..10
                 | (((t >> 11) & 0x3Fu) << 12)     // 6 bits -> 12..17
                 | ((t >> 17) << 19);              // 5 bits -> 19..23

    // Load the 4 coupled amplitudes (each a float4 over the batch dim).
    float4 s00 = state[idx];                 // q5=0, q12=0  -> col 0
    float4 s01 = state[idx + S12_V];         // q5=0, q12=1  -> col 1
    float4 s10 = state[idx + S5_V];          // q5=1, q12=0  -> col 2
    float4 s11 = state[idx + S5_V + S12_V];  // q5=1, q12=1  -> col 3

    float p[16];
#pragma unroll
    for (int i = 0; i < 16; ++i) p[i] = __ldg(pauli + i);

#pragma unroll
    for (int r = 0; r < 4; ++r) {
        float a = p[r * 4 + 0], b = p[r * 4 + 1], c = p[r * 4 + 2], d = p[r * 4 + 3];
        float4 o;
        o.x = fmaf(a, s00.x, fmaf(b, s01.x, fmaf(c, s10.x, d * s11.x)));
        o.y = fmaf(a, s00.y, fmaf(b, s01.y, fmaf(c, s10.y, d * s11.y)));
        o.z = fmaf(a, s00.z, fmaf(b, s01.z, fmaf(c, s10.z, d * s11.z)));
        o.w = fmaf(a, s00.w, fmaf(b, s01.w, fmaf(c, s10.w, d * s11.w)));
        unsigned dst = idx + (r >> 1) * S5_V + (r & 1) * S12_V;
        out[dst] = o;
    }
}

extern "C" void kernel_launch(void* const* d_in, const int* in_sizes, int n_in,
                              void* d_out, int out_size)
{
    const float4* state = (const float4*)d_in[0];   // 2^26 floats = 2^24 float4
    const float*  pauli = (const float*)d_in[1];    // 16 floats
    float4*       out   = (float4*)d_out;

    const unsigned n_threads = 1u << 22;            // one per rest-index
    gate2q_kernel<<<n_threads / 256, 256>>>(state, pauli, out);
}